// round 1
// baseline (speedup 1.0000x reference)
#include <cuda_runtime.h>
#include <math.h>

#define B_   16
#define S_   2048
#define D_   128
#define H_   4
#define DH_  32
#define FF_  512
#define L_   4
#define OUT_ 30
#define M_   (B_*S_)   // 32768

// ---------------- scratch (device globals; no allocation allowed) ----------------
__device__ float g_q[B_*H_*S_*DH_];
__device__ float g_k[B_*H_*S_*DH_];
__device__ float g_v[B_*H_*S_*DH_];
__device__ float g_attn[M_*D_];
__device__ float g_h[M_*D_];
__device__ float g_tmp[M_*D_];
__device__ float g_ff[(size_t)M_*FF_];

// ---------------------------------------------------------------------------------
// Generic SGEMM: C[M,N] = A[M,K] @ W[N,K]^T + bias, with optional epilogues.
// BM=128, BN=64, BK=16; 256 threads; 8x4 per-thread microtile.
// EPI: 0 = bias only, 1 = bias+relu, 2 = bias+residual
// QKV: true = scatter columns into q/k/v buffers laid out [B,H,S,DH]
// ---------------------------------------------------------------------------------
template<int EPI, bool QKV>
__global__ __launch_bounds__(256)
void gemm_kernel(const float* __restrict__ A, const float* __restrict__ W,
                 const float* __restrict__ bias, const float* __restrict__ R,
                 float* __restrict__ C,
                 float* __restrict__ qo, float* __restrict__ ko, float* __restrict__ vo,
                 int N, int K)
{
    __shared__ float As[16*132];
    __shared__ float Bs[16*68];

    const int t   = threadIdx.x;
    const int tx  = t & 15;
    const int ty  = t >> 4;
    const int row0 = blockIdx.y * 128;
    const int col0 = blockIdx.x * 64;

    float acc[8][4];
#pragma unroll
    for (int i = 0; i < 8; i++)
#pragma unroll
        for (int j = 0; j < 4; j++) acc[i][j] = 0.f;

    for (int k0 = 0; k0 < K; k0 += 16) {
        // --- load A tile 128x16 (transposed into As[k][row]) ---
#pragma unroll
        for (int i = 0; i < 2; i++) {
            int f  = t + i * 256;
            int r  = f >> 2;
            int c4 = f & 3;
            float4 av = *reinterpret_cast<const float4*>(&A[(size_t)(row0 + r) * K + k0 + c4 * 4]);
            As[(c4*4+0)*132 + r] = av.x;
            As[(c4*4+1)*132 + r] = av.y;
            As[(c4*4+2)*132 + r] = av.z;
            As[(c4*4+3)*132 + r] = av.w;
        }
        // --- load W tile 64x16 (transposed into Bs[k][n]) ---
        {
            int n  = t >> 2;
            int c4 = t & 3;
            float4 wv = *reinterpret_cast<const float4*>(&W[(size_t)(col0 + n) * K + k0 + c4 * 4]);
            Bs[(c4*4+0)*68 + n] = wv.x;
            Bs[(c4*4+1)*68 + n] = wv.y;
            Bs[(c4*4+2)*68 + n] = wv.z;
            Bs[(c4*4+3)*68 + n] = wv.w;
        }
        __syncthreads();

#pragma unroll
        for (int kk = 0; kk < 16; kk++) {
            float4 a0 = *reinterpret_cast<const float4*>(&As[kk*132 + ty*8]);
            float4 a1 = *reinterpret_cast<const float4*>(&As[kk*132 + ty*8 + 4]);
            float4 bv = *reinterpret_cast<const float4*>(&Bs[kk*68 + tx*4]);
            float a[8] = {a0.x, a0.y, a0.z, a0.w, a1.x, a1.y, a1.z, a1.w};
            float b[4] = {bv.x, bv.y, bv.z, bv.w};
#pragma unroll
            for (int i = 0; i < 8; i++)
#pragma unroll
                for (int j = 0; j < 4; j++)
                    acc[i][j] += a[i] * b[j];
        }
        __syncthreads();
    }

    // --- epilogue ---
#pragma unroll
    for (int i = 0; i < 8; i++) {
        const int m  = row0 + ty * 8 + i;
        const int n0 = col0 + tx * 4;
        if (QKV) {
#pragma unroll
            for (int j = 0; j < 4; j++) {
                int n = n0 + j;
                float val = acc[i][j] + bias[n];
                int which = n >> 7;        // 0=q 1=k 2=v
                int hh    = (n >> 5) & 3;  // head
                int dd    = n & 31;        // dim within head
                int bb    = m >> 11;       // batch (S=2048)
                int ss    = m & 2047;      // seq
                float* dst = (which == 0) ? qo : ((which == 1) ? ko : vo);
                dst[((size_t)(bb * H_ + hh) * S_ + ss) * DH_ + dd] = val;
            }
        } else {
            float4 bsv = *reinterpret_cast<const float4*>(&bias[n0]);
            float4 val = make_float4(acc[i][0] + bsv.x, acc[i][1] + bsv.y,
                                     acc[i][2] + bsv.z, acc[i][3] + bsv.w);
            if (EPI == 1) {
                val.x = fmaxf(val.x, 0.f); val.y = fmaxf(val.y, 0.f);
                val.z = fmaxf(val.z, 0.f); val.w = fmaxf(val.w, 0.f);
            }
            if (EPI == 2) {
                float4 rv = *reinterpret_cast<const float4*>(&R[(size_t)m * N + n0]);
                val.x += rv.x; val.y += rv.y; val.z += rv.z; val.w += rv.w;
            }
            *reinterpret_cast<float4*>(&C[(size_t)m * N + n0]) = val;
        }
    }
}

// ---------------------------------------------------------------------------------
// Flash attention (non-causal, full softmax over S). One thread = one query row.
// Block = 128 threads = 128 queries; K/V tiles of 32 rows in smem (broadcast reads).
// q/k/v layout: [B*H, S, DH]; output merged-head layout [B, S, D].
// ---------------------------------------------------------------------------------
__global__ __launch_bounds__(128)
void attn_kernel(const float* __restrict__ q, const float* __restrict__ k,
                 const float* __restrict__ v, float* __restrict__ out)
{
    __shared__ float Ks[32*36];
    __shared__ float Vs[32*36];

    const int tid = threadIdx.x;
    const int bh  = blockIdx.y;
    const int b   = bh >> 2;
    const int h   = bh & 3;
    const int s   = blockIdx.x * 128 + tid;

    const float scale = 0.17677669529663687f; // 1/sqrt(32)
    const float* qp = q + ((size_t)bh * S_ + s) * DH_;

    float qr[32];
#pragma unroll
    for (int d4 = 0; d4 < 8; d4++) {
        float4 qv = *reinterpret_cast<const float4*>(&qp[d4*4]);
        qr[d4*4+0] = qv.x * scale;
        qr[d4*4+1] = qv.y * scale;
        qr[d4*4+2] = qv.z * scale;
        qr[d4*4+3] = qv.w * scale;
    }

    float mx = -1e30f, l = 0.f;
    float o[32];
#pragma unroll
    for (int d = 0; d < 32; d++) o[d] = 0.f;

    const int r  = tid >> 2;  // 0..31: smem row this thread loads
    const int c4 = tid & 3;

    for (int j0 = 0; j0 < S_; j0 += 32) {
        const float* kb = k + ((size_t)bh * S_ + j0 + r) * DH_;
        const float* vb = v + ((size_t)bh * S_ + j0 + r) * DH_;
        *reinterpret_cast<float4*>(&Ks[r*36 + c4*4])      = *reinterpret_cast<const float4*>(&kb[c4*4]);
        *reinterpret_cast<float4*>(&Ks[r*36 + c4*4 + 16]) = *reinterpret_cast<const float4*>(&kb[c4*4 + 16]);
        *reinterpret_cast<float4*>(&Vs[r*36 + c4*4])      = *reinterpret_cast<const float4*>(&vb[c4*4]);
        *reinterpret_cast<float4*>(&Vs[r*36 + c4*4 + 16]) = *reinterpret_cast<const float4*>(&vb[c4*4 + 16]);
        __syncthreads();

        float sc[32];
#pragma unroll
        for (int j = 0; j < 32; j++) {
            const float4* kr = reinterpret_cast<const float4*>(&Ks[j*36]);
            float acc = 0.f;
#pragma unroll
            for (int d4 = 0; d4 < 8; d4++) {
                float4 kv = kr[d4];
                acc += qr[d4*4+0]*kv.x + qr[d4*4+1]*kv.y + qr[d4*4+2]*kv.z + qr[d4*4+3]*kv.w;
            }
            sc[j] = acc;
        }

        float tm = sc[0];
#pragma unroll
        for (int j = 1; j < 32; j++) tm = fmaxf(tm, sc[j]);
        float mn   = fmaxf(mx, tm);
        float corr = __expf(mx - mn);
        l *= corr;
#pragma unroll
        for (int d = 0; d < 32; d++) o[d] *= corr;

#pragma unroll
        for (int j = 0; j < 32; j++) {
            float p = __expf(sc[j] - mn);
            l += p;
            const float4* vr = reinterpret_cast<const float4*>(&Vs[j*36]);
#pragma unroll
            for (int d4 = 0; d4 < 8; d4++) {
                float4 vv = vr[d4];
                o[d4*4+0] += p * vv.x;
                o[d4*4+1] += p * vv.y;
                o[d4*4+2] += p * vv.z;
                o[d4*4+3] += p * vv.w;
            }
        }
        mx = mn;
        __syncthreads();
    }

    const float inv = 1.f / l;
    float* op = out + ((size_t)(b * S_ + s)) * D_ + h * DH_;
#pragma unroll
    for (int d4 = 0; d4 < 8; d4++) {
        float4 ov = make_float4(o[d4*4+0]*inv, o[d4*4+1]*inv, o[d4*4+2]*inv, o[d4*4+3]*inv);
        *reinterpret_cast<float4*>(&op[d4*4]) = ov;
    }
}

// ---------------------------------------------------------------------------------
// LayerNorm over last dim (128). One warp per row; 8 rows per 256-thread block.
// ---------------------------------------------------------------------------------
__global__ __launch_bounds__(256)
void ln_kernel(const float* __restrict__ in, const float* __restrict__ g,
               const float* __restrict__ bb, float* __restrict__ out)
{
    const int warp = threadIdx.x >> 5;
    const int lane = threadIdx.x & 31;
    const size_t row = (size_t)blockIdx.x * 8 + warp;

    const float4* rp = reinterpret_cast<const float4*>(in + row * D_);
    float4 xv = rp[lane];
    float s  = xv.x + xv.y + xv.z + xv.w;
    float sq = xv.x*xv.x + xv.y*xv.y + xv.z*xv.z + xv.w*xv.w;
#pragma unroll
    for (int off = 16; off > 0; off >>= 1) {
        s  += __shfl_xor_sync(0xffffffffu, s,  off);
        sq += __shfl_xor_sync(0xffffffffu, sq, off);
    }
    float mean = s * (1.f / 128.f);
    float var  = sq * (1.f / 128.f) - mean * mean;
    float rstd = rsqrtf(var + 1e-5f);

    float4 gv = reinterpret_cast<const float4*>(g)[lane];
    float4 bv = reinterpret_cast<const float4*>(bb)[lane];
    float4 yv;
    yv.x = (xv.x - mean) * rstd * gv.x + bv.x;
    yv.y = (xv.y - mean) * rstd * gv.y + bv.y;
    yv.z = (xv.z - mean) * rstd * gv.z + bv.z;
    yv.w = (xv.w - mean) * rstd * gv.w + bv.w;
    reinterpret_cast<float4*>(out + row * D_)[lane] = yv;
}

// ---------------------------------------------------------------------------------
// Final head: last-token FC -> softmax -> exact _rebalance scan replica.
// One block. Threads 0..479 compute logits; threads 0..15 do per-batch epilogue.
// ---------------------------------------------------------------------------------
__global__ __launch_bounds__(512)
void head_kernel(const float* __restrict__ hbuf, const float* __restrict__ fcw,
                 const float* __restrict__ fcb, float* __restrict__ out)
{
    __shared__ float logits[B_][OUT_];
    const int t = threadIdx.x;
    if (t < B_ * OUT_) {
        int b = t / OUT_;
        int o = t % OUT_;
        const float* hr = hbuf + ((size_t)(b * S_ + (S_ - 1))) * D_;
        float acc = fcb[o];
        for (int d = 0; d < D_; d++) acc += hr[d] * fcw[o * D_ + d];
        logits[b][o] = acc;
    }
    __syncthreads();
    if (t < B_) {
        const float UB = 0.3f, LB = 0.0f;
        float wv[OUT_], old[OUT_], wc[OUT_], res[OUT_];
        // softmax
        float mx = -1e30f;
        for (int o = 0; o < OUT_; o++) mx = fmaxf(mx, logits[t][o]);
        float sum = 0.f;
        for (int o = 0; o < OUT_; o++) { wv[o] = expf(logits[t][o] - mx); sum += wv[o]; }
        float inv = 1.f / sum;
        for (int o = 0; o < OUT_; o++) wv[o] *= inv;
        // rebalance (exact replica of the scan body)
        bool done = false;
        for (int o = 0; o < OUT_; o++) {
            old[o] = wv[o];
            wc[o]  = fminf(fmaxf(wv[o], LB), UB);
            res[o] = wv[o];
        }
        for (int it = 0; it < 16; it++) {
            float leftover = 0.f;
            for (int o = 0; o < OUT_; o++) leftover += old[o] - wc[o];
            float denom = 0.f;
            float noms[OUT_];
            for (int o = 0; o < OUT_; o++) {
                noms[o] = (wc[o] != UB) ? wc[o] : 0.f;
                denom += noms[o];
            }
            if (denom == 0.f) denom = 1.f;
            float cand[OUT_];
            bool any = false;
            for (int o = 0; o < OUT_; o++) {
                cand[o] = wc[o] + leftover * noms[o] / denom;
                if (cand[o] > UB) any = true;
            }
            if (!done)
                for (int o = 0; o < OUT_; o++) res[o] = cand[o];
            done = done || !any;
            if (!done) {
                for (int o = 0; o < OUT_; o++) {
                    old[o] = cand[o];
                    wc[o]  = fminf(fmaxf(cand[o], LB), UB);
                }
            }
        }
        for (int o = 0; o < OUT_; o++) out[t * OUT_ + o] = res[o];
    }
}

// ---------------------------------------------------------------------------------
extern "C" void kernel_launch(void* const* d_in, const int* in_sizes, int n_in,
                              void* d_out, int out_size)
{
    const float* x   = (const float*)d_in[0];
    const float* ipw = (const float*)d_in[1];
    const float* ipb = (const float*)d_in[2];
    const float* ow  = (const float*)d_in[3];
    const float* ob  = (const float*)d_in[4];
    const float* l1g = (const float*)d_in[5];
    const float* l1b = (const float*)d_in[6];
    const float* f1w = (const float*)d_in[7];
    const float* f1b = (const float*)d_in[8];
    const float* f2w = (const float*)d_in[9];
    const float* f2b = (const float*)d_in[10];
    const float* l2g = (const float*)d_in[11];
    const float* l2b = (const float*)d_in[12];
    const float* fcw = (const float*)d_in[13];
    const float* fcb = (const float*)d_in[14];

    float *q, *k, *v, *attn, *h, *tmp, *ff;
    cudaGetSymbolAddress((void**)&q,    g_q);
    cudaGetSymbolAddress((void**)&k,    g_k);
    cudaGetSymbolAddress((void**)&v,    g_v);
    cudaGetSymbolAddress((void**)&attn, g_attn);
    cudaGetSymbolAddress((void**)&h,    g_h);
    cudaGetSymbolAddress((void**)&tmp,  g_tmp);
    cudaGetSymbolAddress((void**)&ff,   g_ff);

    for (int l = 0; l < L_; l++) {
        const float* hin = (l == 0) ? x : h;

        // QKV projection (fused head-split scatter)
        gemm_kernel<0, true><<<dim3(3*D_/64, M_/128), 256>>>(
            hin, ipw + (size_t)l * 3*D_*D_, ipb + (size_t)l * 3*D_,
            nullptr, nullptr, q, k, v, 3*D_, D_);

        // Flash attention
        attn_kernel<<<dim3(S_/128, B_*H_), 128>>>(q, k, v, attn);

        // Out projection + bias + residual(hin)
        gemm_kernel<2, false><<<dim3(D_/64, M_/128), 256>>>(
            attn, ow + (size_t)l * D_*D_, ob + (size_t)l * D_,
            hin, tmp, nullptr, nullptr, nullptr, D_, D_);

        // LN1
        ln_kernel<<<M_/8, 256>>>(tmp, l1g + (size_t)l * D_, l1b + (size_t)l * D_, h);

        // FF1 + relu
        gemm_kernel<1, false><<<dim3(FF_/64, M_/128), 256>>>(
            h, f1w + (size_t)l * FF_*D_, f1b + (size_t)l * FF_,
            nullptr, ff, nullptr, nullptr, nullptr, FF_, D_);

        // FF2 + bias + residual(h)
        gemm_kernel<2, false><<<dim3(D_/64, M_/128), 256>>>(
            ff, f2w + (size_t)l * D_*FF_, f2b + (size_t)l * D_,
            h, tmp, nullptr, nullptr, nullptr, D_, FF_);

        // LN2
        ln_kernel<<<M_/8, 256>>>(tmp, l2g + (size_t)l * D_, l2b + (size_t)l * D_, h);
    }

    head_kernel<<<1, 512>>>(h, fcw, fcb, (float*)d_out);
}

// round 3
// speedup vs baseline: 5.3512x; 5.3512x over previous
#include <cuda_runtime.h>
#include <cuda_bf16.h>
#include <cstdint>
#include <math.h>

#define B_   16
#define S_   2048
#define D_   128
#define H_   4
#define DH_  32
#define FF_  512
#define L_   4
#define OUT_ 30
#define M_   (B_*S_)   // 32768

// ======================= warp MMA helper (sm_80+ portable) =======================
// D = A(16x16 bf16 row) @ B(16x8 bf16 col) + D, fp32 accum.
__device__ __forceinline__ void mma16816(float* d, const uint32_t* a, const uint32_t* b) {
    asm volatile("mma.sync.aligned.m16n8k16.row.col.f32.bf16.bf16.f32 "
        "{%0,%1,%2,%3}, {%4,%5,%6,%7}, {%8,%9}, {%0,%1,%2,%3};"
        : "+f"(d[0]), "+f"(d[1]), "+f"(d[2]), "+f"(d[3])
        : "r"(a[0]), "r"(a[1]), "r"(a[2]), "r"(a[3]), "r"(b[0]), "r"(b[1]));
}
__device__ __forceinline__ uint32_t packbf2(float x, float y) {
    __nv_bfloat162 p = __floats2bfloat162_rn(x, y);
    return *(uint32_t*)&p;
}

// ======================= scratch (device globals) =======================
__device__ __nv_bfloat16 g_qb[B_*H_*S_*DH_];
__device__ __nv_bfloat16 g_kb[B_*H_*S_*DH_];
__device__ __nv_bfloat16 g_vb[B_*H_*S_*DH_];
__device__ __nv_bfloat16 g_attnb[M_*D_];
__device__ __nv_bfloat16 g_hb[M_*D_];
__device__ float         g_h[M_*D_];
__device__ float         g_tmp[M_*D_];
__device__ __nv_bfloat16 g_ffb[(size_t)M_*FF_];
__device__ __nv_bfloat16 g_wip[L_*3*D_*D_];
__device__ __nv_bfloat16 g_wout[L_*D_*D_];
__device__ __nv_bfloat16 g_wf1[L_*FF_*D_];
__device__ __nv_bfloat16 g_wf2[L_*D_*FF_];

// ======================= fp32 -> bf16 conversion =======================
__global__ __launch_bounds__(256) void cvt_kernel(const float* __restrict__ s,
                                                  __nv_bfloat16* __restrict__ d, int n) {
    int i = (blockIdx.x * 256 + threadIdx.x) * 4;
    if (i < n) {
        float4 v = *reinterpret_cast<const float4*>(s + i);
        uint2 u = make_uint2(packbf2(v.x, v.y), packbf2(v.z, v.w));
        *reinterpret_cast<uint2*>(d + i) = u;
    }
}

// ======================= bf16 MMA GEMM =======================
// C[128x128 tile] = A[M,K]bf16 @ W[N,K]bf16^T (+bias, epilogue), fp32 accum.
// 256 threads = 8 warps as 2(M) x 4(N); warp tile 64x32.
// EPI 0: +bias, scatter q/k/v bf16 [b,h,s,32]   (blockIdx.x selects q/k/v)
// EPI 1: +bias, relu -> bf16 out [M, Nstride]
// EPI 2: +bias, +residual(fp32) -> fp32 out [M,128]
#define AS_STRIDE 40
template<int EPI>
__global__ __launch_bounds__(256)
void mm_kernel(const __nv_bfloat16* __restrict__ A, const __nv_bfloat16* __restrict__ W,
               const float* __restrict__ bias, const float* __restrict__ R,
               float* __restrict__ outF, __nv_bfloat16* __restrict__ outB,
               __nv_bfloat16* __restrict__ qo, __nv_bfloat16* __restrict__ ko,
               __nv_bfloat16* __restrict__ vo, int Nstride, int K)
{
    __shared__ __nv_bfloat16 As[128 * AS_STRIDE];
    __shared__ __nv_bfloat16 Bs[128 * AS_STRIDE];
    __shared__ float bias_s[128];

    const int t    = threadIdx.x;
    const int wid  = t >> 5;
    const int lane = t & 31;
    const int g    = lane >> 2;
    const int tq   = lane & 3;
    const int wm   = wid >> 2;      // 0..1
    const int wn   = wid & 3;       // 0..3
    const int row0 = blockIdx.y * 128;
    const int n0   = blockIdx.x * 128;

    if (t < 128) bias_s[t] = bias[n0 + t];

    float acc[4][4][4];
#pragma unroll
    for (int mf = 0; mf < 4; mf++)
#pragma unroll
        for (int nf = 0; nf < 4; nf++)
#pragma unroll
            for (int e = 0; e < 4; e++) acc[mf][nf][e] = 0.f;

    const int nkt = K >> 5;
    for (int kt = 0; kt < nkt; kt++) {
        const int k0 = kt << 5;
        // load A,B tiles: 128 rows x 32 cols each = 512 uint4; 2 per thread each
#pragma unroll
        for (int i = 0; i < 2; i++) {
            int u = t + (i << 8);
            int r = u >> 2, q = u & 3;
            *reinterpret_cast<uint4*>(&As[r * AS_STRIDE + q * 8]) =
                *reinterpret_cast<const uint4*>(&A[(size_t)(row0 + r) * K + k0 + q * 8]);
            *reinterpret_cast<uint4*>(&Bs[r * AS_STRIDE + q * 8]) =
                *reinterpret_cast<const uint4*>(&W[(size_t)(n0 + r) * K + k0 + q * 8]);
        }
        __syncthreads();

#pragma unroll
        for (int ks = 0; ks < 2; ks++) {
            const int kk = ks << 4;
            uint32_t af[4][4], bf[4][2];
#pragma unroll
            for (int mf = 0; mf < 4; mf++) {
                const int mr = wm * 64 + mf * 16;
                af[mf][0] = *reinterpret_cast<const uint32_t*>(&As[(mr + g)     * AS_STRIDE + kk + tq * 2]);
                af[mf][1] = *reinterpret_cast<const uint32_t*>(&As[(mr + g + 8) * AS_STRIDE + kk + tq * 2]);
                af[mf][2] = *reinterpret_cast<const uint32_t*>(&As[(mr + g)     * AS_STRIDE + kk + tq * 2 + 8]);
                af[mf][3] = *reinterpret_cast<const uint32_t*>(&As[(mr + g + 8) * AS_STRIDE + kk + tq * 2 + 8]);
            }
#pragma unroll
            for (int nf = 0; nf < 4; nf++) {
                const int nr = wn * 32 + nf * 8 + g;
                bf[nf][0] = *reinterpret_cast<const uint32_t*>(&Bs[nr * AS_STRIDE + kk + tq * 2]);
                bf[nf][1] = *reinterpret_cast<const uint32_t*>(&Bs[nr * AS_STRIDE + kk + tq * 2 + 8]);
            }
#pragma unroll
            for (int mf = 0; mf < 4; mf++)
#pragma unroll
                for (int nf = 0; nf < 4; nf++)
                    mma16816(acc[mf][nf], af[mf], bf[nf]);
        }
        __syncthreads();
    }

    // ---- epilogue ----
#pragma unroll
    for (int mf = 0; mf < 4; mf++) {
        const int m0 = row0 + wm * 64 + mf * 16 + g;
        const int m1 = m0 + 8;
#pragma unroll
        for (int nf = 0; nf < 4; nf++) {
            const int c = wn * 32 + nf * 8 + tq * 2;   // block-local col (0..127)
            float v0 = acc[mf][nf][0] + bias_s[c];
            float v1 = acc[mf][nf][1] + bias_s[c + 1];
            float v2 = acc[mf][nf][2] + bias_s[c];
            float v3 = acc[mf][nf][3] + bias_s[c + 1];
            if (EPI == 0) {
                __nv_bfloat16* dst = (blockIdx.x == 0) ? qo : ((blockIdx.x == 1) ? ko : vo);
                const int hh = c >> 5, dd = c & 31;
                int b0i = m0 >> 11, s0i = m0 & 2047;
                int b1i = m1 >> 11, s1i = m1 & 2047;
                uint32_t p0 = packbf2(v0, v1), p1 = packbf2(v2, v3);
                *reinterpret_cast<uint32_t*>(dst + ((size_t)(b0i * H_ + hh) * S_ + s0i) * DH_ + dd) = p0;
                *reinterpret_cast<uint32_t*>(dst + ((size_t)(b1i * H_ + hh) * S_ + s1i) * DH_ + dd) = p1;
            } else if (EPI == 1) {
                uint32_t p0 = packbf2(fmaxf(v0, 0.f), fmaxf(v1, 0.f));
                uint32_t p1 = packbf2(fmaxf(v2, 0.f), fmaxf(v3, 0.f));
                *reinterpret_cast<uint32_t*>(outB + (size_t)m0 * Nstride + n0 + c) = p0;
                *reinterpret_cast<uint32_t*>(outB + (size_t)m1 * Nstride + n0 + c) = p1;
            } else {
                float2 r0 = *reinterpret_cast<const float2*>(R + (size_t)m0 * 128 + c);
                float2 r1 = *reinterpret_cast<const float2*>(R + (size_t)m1 * 128 + c);
                *reinterpret_cast<float2*>(outF + (size_t)m0 * 128 + c) = make_float2(v0 + r0.x, v1 + r0.y);
                *reinterpret_cast<float2*>(outF + (size_t)m1 * 128 + c) = make_float2(v2 + r1.x, v3 + r1.y);
            }
        }
    }
}

// ======================= MMA flash attention =======================
// CTA: one (bh, 128-query block). 8 warps; warp w owns queries w*16..w*16+15.
// Key tiles of 64. S = Q@K^T (mma), p=exp(s*scale) in-register, O += P@V (mma).
#define VT_STRIDE 72
__global__ __launch_bounds__(256)
void attn_kernel(const __nv_bfloat16* __restrict__ q, const __nv_bfloat16* __restrict__ k,
                 const __nv_bfloat16* __restrict__ v, __nv_bfloat16* __restrict__ out)
{
    __shared__ __nv_bfloat16 Qs[128 * AS_STRIDE];
    __shared__ __nv_bfloat16 Ks[64 * AS_STRIDE];
    __shared__ __nv_bfloat16 Vt[32 * VT_STRIDE];   // V^T: [dh][key]

    const int t    = threadIdx.x;
    const int wid  = t >> 5;
    const int lane = t & 31;
    const int g    = lane >> 2;
    const int tq   = lane & 3;
    const int bh   = blockIdx.y, b = bh >> 2, h = bh & 3;
    const int q0   = blockIdx.x * 128;
    const float SCALE = 0.17677669529663687f;  // 1/sqrt(32)

    // load Q tile: 128 rows x 32 cols = 512 uint4
#pragma unroll
    for (int i = 0; i < 2; i++) {
        int u = t + (i << 8);
        int r = u >> 2, qq = u & 3;
        *reinterpret_cast<uint4*>(&Qs[r * AS_STRIDE + qq * 8]) =
            *reinterpret_cast<const uint4*>(&q[((size_t)bh * S_ + q0 + r) * DH_ + qq * 8]);
    }

    float o[4][4];      // O accumulator: 4 dh-frags x 4
    float lg = 0.f, lg8 = 0.f;
#pragma unroll
    for (int nf = 0; nf < 4; nf++)
#pragma unroll
        for (int e = 0; e < 4; e++) o[nf][e] = 0.f;

    __syncthreads();

    for (int j0 = 0; j0 < S_; j0 += 64) {
        // K tile: 64 x 32 = 256 uint4, one per thread
        {
            int r = t >> 2, qq = t & 3;
            *reinterpret_cast<uint4*>(&Ks[r * AS_STRIDE + qq * 8]) =
                *reinterpret_cast<const uint4*>(&k[((size_t)bh * S_ + j0 + r) * DH_ + qq * 8]);
        }
        // V^T tile: thread owns (key = t>>2, 8 dh values)
        {
            int key = t >> 2, c4 = t & 3;
            union { uint4 u4; __nv_bfloat16 e[8]; } vv;
            vv.u4 = *reinterpret_cast<const uint4*>(&v[((size_t)bh * S_ + j0 + key) * DH_ + c4 * 8]);
#pragma unroll
            for (int e8 = 0; e8 < 8; e8++)
                Vt[(c4 * 8 + e8) * VT_STRIDE + key] = vv.e[e8];
        }
        __syncthreads();

        // S = Q @ K^T : warp tile 16(q) x 64(keys), k-dim 32
        float sc[8][4];
#pragma unroll
        for (int nf = 0; nf < 8; nf++)
#pragma unroll
            for (int e = 0; e < 4; e++) sc[nf][e] = 0.f;

#pragma unroll
        for (int ks = 0; ks < 2; ks++) {
            const int kk = ks << 4;
            uint32_t af[4];
            const int mr = wid * 16;
            af[0] = *reinterpret_cast<const uint32_t*>(&Qs[(mr + g)     * AS_STRIDE + kk + tq * 2]);
            af[1] = *reinterpret_cast<const uint32_t*>(&Qs[(mr + g + 8) * AS_STRIDE + kk + tq * 2]);
            af[2] = *reinterpret_cast<const uint32_t*>(&Qs[(mr + g)     * AS_STRIDE + kk + tq * 2 + 8]);
            af[3] = *reinterpret_cast<const uint32_t*>(&Qs[(mr + g + 8) * AS_STRIDE + kk + tq * 2 + 8]);
#pragma unroll
            for (int nf = 0; nf < 8; nf++) {
                uint32_t bfr[2];
                const int nr = nf * 8 + g;
                bfr[0] = *reinterpret_cast<const uint32_t*>(&Ks[nr * AS_STRIDE + kk + tq * 2]);
                bfr[1] = *reinterpret_cast<const uint32_t*>(&Ks[nr * AS_STRIDE + kk + tq * 2 + 8]);
                mma16816(sc[nf], af, bfr);
            }
        }

        // softmax numerator + repack as PV A-fragments
        uint32_t pb[8][2];  // [score n-frag][pack of (c0,c1) and (c2,c3)]
#pragma unroll
        for (int nf = 0; nf < 8; nf++) {
            float p0 = __expf(sc[nf][0] * SCALE);
            float p1 = __expf(sc[nf][1] * SCALE);
            float p2 = __expf(sc[nf][2] * SCALE);
            float p3 = __expf(sc[nf][3] * SCALE);
            lg  += p0 + p1;
            lg8 += p2 + p3;
            pb[nf][0] = packbf2(p0, p1);
            pb[nf][1] = packbf2(p2, p3);
        }

        // O += P @ V : k-dim 64 keys (4 k-frags), n-dim 32 dh (4 n-frags)
#pragma unroll
        for (int kf = 0; kf < 4; kf++) {
            uint32_t af[4];
            af[0] = pb[2 * kf][0];
            af[1] = pb[2 * kf][1];
            af[2] = pb[2 * kf + 1][0];
            af[3] = pb[2 * kf + 1][1];
#pragma unroll
            for (int nf = 0; nf < 4; nf++) {
                uint32_t bfr[2];
                const int nr = nf * 8 + g;
                bfr[0] = *reinterpret_cast<const uint32_t*>(&Vt[nr * VT_STRIDE + kf * 16 + tq * 2]);
                bfr[1] = *reinterpret_cast<const uint32_t*>(&Vt[nr * VT_STRIDE + kf * 16 + tq * 2 + 8]);
                mma16816(o[nf], af, bfr);
            }
        }
        __syncthreads();
    }

    // reduce l across the quad (lanes sharing g)
    lg  += __shfl_xor_sync(0xffffffffu, lg, 1);
    lg  += __shfl_xor_sync(0xffffffffu, lg, 2);
    lg8 += __shfl_xor_sync(0xffffffffu, lg8, 1);
    lg8 += __shfl_xor_sync(0xffffffffu, lg8, 2);
    const float inv0 = 1.f / lg;
    const float inv1 = 1.f / lg8;

    const int r0 = q0 + wid * 16 + g;
    const int r1 = r0 + 8;
#pragma unroll
    for (int nf = 0; nf < 4; nf++) {
        const int dd = nf * 8 + tq * 2;
        uint32_t p0 = packbf2(o[nf][0] * inv0, o[nf][1] * inv0);
        uint32_t p1 = packbf2(o[nf][2] * inv1, o[nf][3] * inv1);
        *reinterpret_cast<uint32_t*>(out + ((size_t)(b * S_ + r0)) * D_ + h * DH_ + dd) = p0;
        *reinterpret_cast<uint32_t*>(out + ((size_t)(b * S_ + r1)) * D_ + h * DH_ + dd) = p1;
    }
}

// ======================= LayerNorm (fp32 in -> fp32 + bf16 out) =======================
__global__ __launch_bounds__(256)
void ln_kernel(const float* __restrict__ in, const float* __restrict__ g,
               const float* __restrict__ bb, float* __restrict__ out,
               __nv_bfloat16* __restrict__ outb)
{
    const int warp = threadIdx.x >> 5;
    const int lane = threadIdx.x & 31;
    const size_t row = (size_t)blockIdx.x * 8 + warp;

    float4 xv = reinterpret_cast<const float4*>(in + row * D_)[lane];
    float s  = xv.x + xv.y + xv.z + xv.w;
    float sq = xv.x*xv.x + xv.y*xv.y + xv.z*xv.z + xv.w*xv.w;
#pragma unroll
    for (int off = 16; off > 0; off >>= 1) {
        s  += __shfl_xor_sync(0xffffffffu, s,  off);
        sq += __shfl_xor_sync(0xffffffffu, sq, off);
    }
    float mean = s * (1.f / 128.f);
    float var  = sq * (1.f / 128.f) - mean * mean;
    float rstd = rsqrtf(var + 1e-5f);

    float4 gv = reinterpret_cast<const float4*>(g)[lane];
    float4 bv = reinterpret_cast<const float4*>(bb)[lane];
    float4 yv;
    yv.x = (xv.x - mean) * rstd * gv.x + bv.x;
    yv.y = (xv.y - mean) * rstd * gv.y + bv.y;
    yv.z = (xv.z - mean) * rstd * gv.z + bv.z;
    yv.w = (xv.w - mean) * rstd * gv.w + bv.w;
    reinterpret_cast<float4*>(out + row * D_)[lane] = yv;
    reinterpret_cast<uint2*>(outb + row * D_)[lane] =
        make_uint2(packbf2(yv.x, yv.y), packbf2(yv.z, yv.w));
}

// ======================= Head: FC -> softmax -> rebalance =======================
__global__ __launch_bounds__(512)
void head_kernel(const float* __restrict__ hbuf, const float* __restrict__ fcw,
                 const float* __restrict__ fcb, float* __restrict__ out)
{
    __shared__ float logits[B_][OUT_];
    const int t = threadIdx.x;
    if (t < B_ * OUT_) {
        int b = t / OUT_;
        int o = t % OUT_;
        const float* hr = hbuf + ((size_t)(b * S_ + (S_ - 1))) * D_;
        float acc = fcb[o];
        for (int d = 0; d < D_; d++) acc += hr[d] * fcw[o * D_ + d];
        logits[b][o] = acc;
    }
    __syncthreads();
    if (t < B_) {
        const float UB = 0.3f, LB = 0.0f;
        float wv[OUT_], old[OUT_], wc[OUT_], res[OUT_];
        float mx = -1e30f;
        for (int o = 0; o < OUT_; o++) mx = fmaxf(mx, logits[t][o]);
        float sum = 0.f;
        for (int o = 0; o < OUT_; o++) { wv[o] = expf(logits[t][o] - mx); sum += wv[o]; }
        float inv = 1.f / sum;
        for (int o = 0; o < OUT_; o++) wv[o] *= inv;
        bool done = false;
        for (int o = 0; o < OUT_; o++) {
            old[o] = wv[o];
            wc[o]  = fminf(fmaxf(wv[o], LB), UB);
            res[o] = wv[o];
        }
        for (int it = 0; it < 16; it++) {
            float leftover = 0.f;
            for (int o = 0; o < OUT_; o++) leftover += old[o] - wc[o];
            float denom = 0.f;
            float noms[OUT_];
            for (int o = 0; o < OUT_; o++) {
                noms[o] = (wc[o] != UB) ? wc[o] : 0.f;
                denom += noms[o];
            }
            if (denom == 0.f) denom = 1.f;
            float cand[OUT_];
            bool any = false;
            for (int o = 0; o < OUT_; o++) {
                cand[o] = wc[o] + leftover * noms[o] / denom;
                if (cand[o] > UB) any = true;
            }
            if (!done)
                for (int o = 0; o < OUT_; o++) res[o] = cand[o];
            done = done || !any;
            if (!done) {
                for (int o = 0; o < OUT_; o++) {
                    old[o] = cand[o];
                    wc[o]  = fminf(fmaxf(cand[o], LB), UB);
                }
            }
        }
        for (int o = 0; o < OUT_; o++) out[t * OUT_ + o] = res[o];
    }
}

// ======================= launch =======================
extern "C" void kernel_launch(void* const* d_in, const int* in_sizes, int n_in,
                              void* d_out, int out_size)
{
    const float* x   = (const float*)d_in[0];
    const float* ipw = (const float*)d_in[1];
    const float* ipb = (const float*)d_in[2];
    const float* ow  = (const float*)d_in[3];
    const float* ob  = (const float*)d_in[4];
    const float* l1g = (const float*)d_in[5];
    const float* l1b = (const float*)d_in[6];
    const float* f1w = (const float*)d_in[7];
    const float* f1b = (const float*)d_in[8];
    const float* f2w = (const float*)d_in[9];
    const float* f2b = (const float*)d_in[10];
    const float* l2g = (const float*)d_in[11];
    const float* l2b = (const float*)d_in[12];
    const float* fcw = (const float*)d_in[13];
    const float* fcb = (const float*)d_in[14];

    __nv_bfloat16 *qb, *kb, *vb, *attnb, *hb, *ffb, *wip, *wout, *wf1, *wf2;
    float *h, *tmp;
    cudaGetSymbolAddress((void**)&qb,    g_qb);
    cudaGetSymbolAddress((void**)&kb,    g_kb);
    cudaGetSymbolAddress((void**)&vb,    g_vb);
    cudaGetSymbolAddress((void**)&attnb, g_attnb);
    cudaGetSymbolAddress((void**)&hb,    g_hb);
    cudaGetSymbolAddress((void**)&h,     g_h);
    cudaGetSymbolAddress((void**)&tmp,   g_tmp);
    cudaGetSymbolAddress((void**)&ffb,   g_ffb);
    cudaGetSymbolAddress((void**)&wip,   g_wip);
    cudaGetSymbolAddress((void**)&wout,  g_wout);
    cudaGetSymbolAddress((void**)&wf1,   g_wf1);
    cudaGetSymbolAddress((void**)&wf2,   g_wf2);

    // weight + input conversions (small; inside graph)
    cvt_kernel<<<(L_*3*D_*D_)/1024, 256>>>(ipw, wip, L_*3*D_*D_);
    cvt_kernel<<<(L_*D_*D_)/1024,   256>>>(ow,  wout, L_*D_*D_);
    cvt_kernel<<<(L_*FF_*D_)/1024,  256>>>(f1w, wf1, L_*FF_*D_);
    cvt_kernel<<<(L_*D_*FF_)/1024,  256>>>(f2w, wf2, L_*D_*FF_);
    cvt_kernel<<<(M_*D_)/1024,      256>>>(x,   hb,  M_*D_);

    for (int l = 0; l < L_; l++) {
        const float* hinF = (l == 0) ? x : h;

        // QKV projection -> q/k/v bf16 [b,h,s,32]
        mm_kernel<0><<<dim3(3, M_/128), 256>>>(
            hb, wip + (size_t)l*3*D_*D_, ipb + (size_t)l*3*D_,
            nullptr, nullptr, nullptr, qb, kb, vb, 3*D_, D_);

        // flash attention
        attn_kernel<<<dim3(S_/128, B_*H_), 256>>>(qb, kb, vb, attnb);

        // out projection + bias + residual -> fp32 tmp
        mm_kernel<2><<<dim3(1, M_/128), 256>>>(
            attnb, wout + (size_t)l*D_*D_, ob + (size_t)l*D_,
            hinF, tmp, nullptr, nullptr, nullptr, nullptr, D_, D_);

        // LN1 -> h (fp32) + hb (bf16)
        ln_kernel<<<M_/8, 256>>>(tmp, l1g + (size_t)l*D_, l1b + (size_t)l*D_, h, hb);

        // FF1 + relu -> ffb (bf16)
        mm_kernel<1><<<dim3(FF_/128, M_/128), 256>>>(
            hb, wf1 + (size_t)l*FF_*D_, f1b + (size_t)l*FF_,
            nullptr, nullptr, ffb, nullptr, nullptr, nullptr, FF_, D_);

        // FF2 + bias + residual(h) -> fp32 tmp
        mm_kernel<2><<<dim3(1, M_/128), 256>>>(
            ffb, wf2 + (size_t)l*D_*FF_, f2b + (size_t)l*D_,
            h, tmp, nullptr, nullptr, nullptr, nullptr, D_, FF_);

        // LN2 -> h (fp32) + hb (bf16)
        ln_kernel<<<M_/8, 256>>>(tmp, l2g + (size_t)l*D_, l2b + (size_t)l*D_, h, hb);
    }

    head_kernel<<<1, 512>>>(h, fcw, fcb, (float*)d_out);
}

// round 4
// speedup vs baseline: 7.0179x; 1.3115x over previous
#include <cuda_runtime.h>
#include <cuda_bf16.h>
#include <cstdint>
#include <math.h>

#define B_   16
#define S_   2048
#define D_   128
#define H_   4
#define DH_  32
#define FF_  512
#define L_   4
#define OUT_ 30
#define M_   (B_*S_)   // 32768

// log2(e) / sqrt(32): folded into Q so softmax is a bare ex2
#define QSCALE 0.25506626866f

// ======================= low-level helpers =======================
__device__ __forceinline__ void mma16816(float* d, const uint32_t* a, const uint32_t* b) {
    asm volatile("mma.sync.aligned.m16n8k16.row.col.f32.bf16.bf16.f32 "
        "{%0,%1,%2,%3}, {%4,%5,%6,%7}, {%8,%9}, {%0,%1,%2,%3};"
        : "+f"(d[0]), "+f"(d[1]), "+f"(d[2]), "+f"(d[3])
        : "r"(a[0]), "r"(a[1]), "r"(a[2]), "r"(a[3]), "r"(b[0]), "r"(b[1]));
}
__device__ __forceinline__ uint32_t packbf2(float x, float y) {
    __nv_bfloat162 p = __floats2bfloat162_rn(x, y);
    return *(uint32_t*)&p;
}
__device__ __forceinline__ float ex2f(float x) {
    float y; asm("ex2.approx.f32 %0, %1;" : "=f"(y) : "f"(x)); return y;
}
__device__ __forceinline__ uint32_t cvta_s(const void* p) {
    return (uint32_t)__cvta_generic_to_shared(p);
}
__device__ __forceinline__ void cp16(uint32_t dst, const void* src) {
    asm volatile("cp.async.cg.shared.global [%0], [%1], 16;" :: "r"(dst), "l"(src));
}
#define CP_COMMIT() asm volatile("cp.async.commit_group;" ::: "memory")
#define CP_WAIT(n)  asm volatile("cp.async.wait_group %0;" :: "n"(n) : "memory")
__device__ __forceinline__ void ldm_x4(uint32_t* r, uint32_t a) {
    asm volatile("ldmatrix.sync.aligned.m8n8.x4.shared.b16 {%0,%1,%2,%3}, [%4];"
        : "=r"(r[0]), "=r"(r[1]), "=r"(r[2]), "=r"(r[3]) : "r"(a));
}
__device__ __forceinline__ void ldm_x4t(uint32_t* r, uint32_t a) {
    asm volatile("ldmatrix.sync.aligned.m8n8.x4.trans.shared.b16 {%0,%1,%2,%3}, [%4];"
        : "=r"(r[0]), "=r"(r[1]), "=r"(r[2]), "=r"(r[3]) : "r"(a));
}

// ======================= scratch (device globals) =======================
__device__ __nv_bfloat16 g_qb[B_*H_*S_*DH_];
__device__ __nv_bfloat16 g_kb[B_*H_*S_*DH_];
__device__ __nv_bfloat16 g_vb[B_*H_*S_*DH_];
__device__ __nv_bfloat16 g_attnb[M_*D_];
__device__ __nv_bfloat16 g_hb[M_*D_];
__device__ float         g_h[M_*D_];
__device__ __nv_bfloat16 g_ffb[(size_t)M_*FF_];
__device__ __nv_bfloat16 g_wip[L_*3*D_*D_];
__device__ __nv_bfloat16 g_wout[L_*D_*D_];
__device__ __nv_bfloat16 g_wf1[L_*FF_*D_];
__device__ __nv_bfloat16 g_wf2[L_*D_*FF_];

// ======================= fp32 -> bf16 conversion =======================
__global__ __launch_bounds__(256) void cvt_kernel(const float* __restrict__ s,
                                                  __nv_bfloat16* __restrict__ d, int n) {
    int i = (blockIdx.x * 256 + threadIdx.x) * 4;
    if (i < n) {
        float4 v = *reinterpret_cast<const float4*>(s + i);
        *reinterpret_cast<uint2*>(d + i) = make_uint2(packbf2(v.x, v.y), packbf2(v.z, v.w));
    }
}

// ======================= pipelined bf16 MMA GEMM =======================
// C[128x128 tile] = A[M,K] @ W[N,K]^T + bias. 8 warps (2M x 4N), warp tile 64x32.
// EPI 0: scatter q/k/v bf16 [b,h,s,32]; q pre-scaled by QSCALE (blockIdx.x picks q/k/v)
// EPI 1: relu -> bf16 [M, Nstride]
// EPI 2: +residual(fp32) -> LayerNorm fused -> fp32 h + bf16 hb
#define TST 40   // smem row stride (elements)
template<int EPI>
__global__ __launch_bounds__(256)
void mm_kernel(const __nv_bfloat16* __restrict__ A, const __nv_bfloat16* __restrict__ W,
               const float* __restrict__ bias, const float* __restrict__ R,
               const float* __restrict__ lng, const float* __restrict__ lnb,
               float* __restrict__ outF, __nv_bfloat16* __restrict__ outB,
               __nv_bfloat16* __restrict__ qo, __nv_bfloat16* __restrict__ ko,
               __nv_bfloat16* __restrict__ vo, int Nstride, int K)
{
    __shared__ __nv_bfloat16 As[2][128*TST];
    __shared__ __nv_bfloat16 Bs[2][128*TST];
    __shared__ float bias_s[128];
    __shared__ float lng_s[128], lnb_s[128];
    __shared__ float redS[128][4], redQ[128][4];

    const int t    = threadIdx.x;
    const int wid  = t >> 5;
    const int lane = t & 31;
    const int g    = lane >> 2;
    const int tq   = lane & 3;
    const int wm   = wid >> 2;
    const int wn   = wid & 3;
    const int row0 = blockIdx.y * 128;
    const int n0   = blockIdx.x * 128;

    if (t < 128) {
        bias_s[t] = bias[n0 + t];
        if (EPI == 2) { lng_s[t] = lng[t]; lnb_s[t] = lnb[t]; }
    }

    const uint32_t sA[2] = { cvta_s(As[0]), cvta_s(As[1]) };
    const uint32_t sB[2] = { cvta_s(Bs[0]), cvta_s(Bs[1]) };

    auto load_tile = [&](int kt, int stg) {
        const int k0 = kt << 5;
#pragma unroll
        for (int i = 0; i < 2; i++) {
            int id = t + (i << 8);
            int r = id >> 2, qq = id & 3;
            cp16(sA[stg] + r * (TST*2) + qq * 16, &A[(size_t)(row0 + r) * K + k0 + qq * 8]);
            cp16(sB[stg] + r * (TST*2) + qq * 16, &W[(size_t)(n0   + r) * K + k0 + qq * 8]);
        }
    };

    float acc[4][4][4];
#pragma unroll
    for (int mf = 0; mf < 4; mf++)
#pragma unroll
        for (int nf = 0; nf < 4; nf++)
#pragma unroll
            for (int e = 0; e < 4; e++) acc[mf][nf][e] = 0.f;

    const int nkt = K >> 5;
    load_tile(0, 0);
    CP_COMMIT();

    // precomputed ldmatrix lane-offsets (element units)
    const int aRow = wm * 64 + (lane & 15);
    const int aColX = (lane >> 4) * 8;
    const int bRow = wn * 32 + (lane & 7) + ((lane >> 4) << 3);
    const int bColX = ((lane >> 3) & 1) * 8;

    for (int kt = 0; kt < nkt; kt++) {
        const int stg = kt & 1;
        if (kt + 1 < nkt) { load_tile(kt + 1, stg ^ 1); CP_COMMIT(); CP_WAIT(1); }
        else CP_WAIT(0);
        __syncthreads();

#pragma unroll
        for (int ks = 0; ks < 2; ks++) {
            const int kk = ks << 4;
            uint32_t af[4][4];
#pragma unroll
            for (int mf = 0; mf < 4; mf++)
                ldm_x4(af[mf], sA[stg] + ((aRow + mf * 16) * TST + kk + aColX) * 2);
            uint32_t bf[4][2];
#pragma unroll
            for (int pp = 0; pp < 2; pp++) {
                uint32_t r4[4];
                ldm_x4(r4, sB[stg] + ((bRow + pp * 16) * TST + kk + bColX) * 2);
                bf[pp*2][0] = r4[0]; bf[pp*2][1] = r4[1];
                bf[pp*2+1][0] = r4[2]; bf[pp*2+1][1] = r4[3];
            }
#pragma unroll
            for (int mf = 0; mf < 4; mf++)
#pragma unroll
                for (int nf = 0; nf < 4; nf++)
                    mma16816(acc[mf][nf], af[mf], bf[nf]);
        }
        __syncthreads();
    }

    // ---- epilogue ----
    if (EPI == 2) {
        // bias + residual into acc, then per-row partial sums
#pragma unroll
        for (int mf = 0; mf < 4; mf++) {
            const int m0 = row0 + wm * 64 + mf * 16 + g;
            const int m1 = m0 + 8;
            float s0 = 0.f, q0 = 0.f, s1 = 0.f, q1 = 0.f;
#pragma unroll
            for (int nf = 0; nf < 4; nf++) {
                const int c = wn * 32 + nf * 8 + tq * 2;
                float2 r0 = *reinterpret_cast<const float2*>(R + (size_t)m0 * 128 + c);
                float2 r1 = *reinterpret_cast<const float2*>(R + (size_t)m1 * 128 + c);
                float v0 = acc[mf][nf][0] + bias_s[c]     + r0.x;
                float v1 = acc[mf][nf][1] + bias_s[c + 1] + r0.y;
                float v2 = acc[mf][nf][2] + bias_s[c]     + r1.x;
                float v3 = acc[mf][nf][3] + bias_s[c + 1] + r1.y;
                acc[mf][nf][0] = v0; acc[mf][nf][1] = v1;
                acc[mf][nf][2] = v2; acc[mf][nf][3] = v3;
                s0 += v0 + v1; q0 += v0*v0 + v1*v1;
                s1 += v2 + v3; q1 += v2*v2 + v3*v3;
            }
            s0 += __shfl_xor_sync(0xffffffffu, s0, 1); s0 += __shfl_xor_sync(0xffffffffu, s0, 2);
            q0 += __shfl_xor_sync(0xffffffffu, q0, 1); q0 += __shfl_xor_sync(0xffffffffu, q0, 2);
            s1 += __shfl_xor_sync(0xffffffffu, s1, 1); s1 += __shfl_xor_sync(0xffffffffu, s1, 2);
            q1 += __shfl_xor_sync(0xffffffffu, q1, 1); q1 += __shfl_xor_sync(0xffffffffu, q1, 2);
            if (tq == 0) {
                const int rl = wm * 64 + mf * 16 + g;
                redS[rl][wn] = s0; redQ[rl][wn] = q0;
                redS[rl + 8][wn] = s1; redQ[rl + 8][wn] = q1;
            }
        }
        __syncthreads();
#pragma unroll
        for (int mf = 0; mf < 4; mf++) {
            const int rl = wm * 64 + mf * 16 + g;
            const int m0 = row0 + rl, m1 = m0 + 8;
            float sum0 = redS[rl][0] + redS[rl][1] + redS[rl][2] + redS[rl][3];
            float sq0  = redQ[rl][0] + redQ[rl][1] + redQ[rl][2] + redQ[rl][3];
            float sum1 = redS[rl+8][0] + redS[rl+8][1] + redS[rl+8][2] + redS[rl+8][3];
            float sq1  = redQ[rl+8][0] + redQ[rl+8][1] + redQ[rl+8][2] + redQ[rl+8][3];
            float mean0 = sum0 * (1.f/128.f);
            float mean1 = sum1 * (1.f/128.f);
            float rstd0 = rsqrtf(sq0 * (1.f/128.f) - mean0*mean0 + 1e-5f);
            float rstd1 = rsqrtf(sq1 * (1.f/128.f) - mean1*mean1 + 1e-5f);
#pragma unroll
            for (int nf = 0; nf < 4; nf++) {
                const int c = wn * 32 + nf * 8 + tq * 2;
                float y0 = (acc[mf][nf][0] - mean0) * rstd0 * lng_s[c]   + lnb_s[c];
                float y1 = (acc[mf][nf][1] - mean0) * rstd0 * lng_s[c+1] + lnb_s[c+1];
                float y2 = (acc[mf][nf][2] - mean1) * rstd1 * lng_s[c]   + lnb_s[c];
                float y3 = (acc[mf][nf][3] - mean1) * rstd1 * lng_s[c+1] + lnb_s[c+1];
                *reinterpret_cast<float2*>(outF + (size_t)m0 * 128 + c) = make_float2(y0, y1);
                *reinterpret_cast<float2*>(outF + (size_t)m1 * 128 + c) = make_float2(y2, y3);
                *reinterpret_cast<uint32_t*>(outB + (size_t)m0 * 128 + c) = packbf2(y0, y1);
                *reinterpret_cast<uint32_t*>(outB + (size_t)m1 * 128 + c) = packbf2(y2, y3);
            }
        }
    } else {
#pragma unroll
        for (int mf = 0; mf < 4; mf++) {
            const int m0 = row0 + wm * 64 + mf * 16 + g;
            const int m1 = m0 + 8;
#pragma unroll
            for (int nf = 0; nf < 4; nf++) {
                const int c = wn * 32 + nf * 8 + tq * 2;
                float v0 = acc[mf][nf][0] + bias_s[c];
                float v1 = acc[mf][nf][1] + bias_s[c + 1];
                float v2 = acc[mf][nf][2] + bias_s[c];
                float v3 = acc[mf][nf][3] + bias_s[c + 1];
                if (EPI == 0) {
                    __nv_bfloat16* dst = (blockIdx.x == 0) ? qo : ((blockIdx.x == 1) ? ko : vo);
                    if (blockIdx.x == 0) { v0 *= QSCALE; v1 *= QSCALE; v2 *= QSCALE; v3 *= QSCALE; }
                    const int hh = c >> 5, dd = c & 31;
                    int b0i = m0 >> 11, s0i = m0 & 2047;
                    int b1i = m1 >> 11, s1i = m1 & 2047;
                    *reinterpret_cast<uint32_t*>(dst + ((size_t)(b0i * H_ + hh) * S_ + s0i) * DH_ + dd) = packbf2(v0, v1);
                    *reinterpret_cast<uint32_t*>(dst + ((size_t)(b1i * H_ + hh) * S_ + s1i) * DH_ + dd) = packbf2(v2, v3);
                } else {
                    *reinterpret_cast<uint32_t*>(outB + (size_t)m0 * Nstride + n0 + c) =
                        packbf2(fmaxf(v0, 0.f), fmaxf(v1, 0.f));
                    *reinterpret_cast<uint32_t*>(outB + (size_t)m1 * Nstride + n0 + c) =
                        packbf2(fmaxf(v2, 0.f), fmaxf(v3, 0.f));
                }
            }
        }
    }
}

// ======================= pipelined MMA flash attention =======================
// CTA: (bh, 128 queries). 8 warps x 16 queries. 64-key tiles, cp.async double buffer.
// Q pre-scaled by log2e/sqrt(dh) -> p = ex2(s). V row-major, PV B-frags via ldmatrix.trans.
__global__ __launch_bounds__(256)
void attn_kernel(const __nv_bfloat16* __restrict__ q, const __nv_bfloat16* __restrict__ k,
                 const __nv_bfloat16* __restrict__ v, __nv_bfloat16* __restrict__ out)
{
    __shared__ __nv_bfloat16 Qs[128*TST];
    __shared__ __nv_bfloat16 Ks[2][64*TST];
    __shared__ __nv_bfloat16 Vs[2][64*TST];

    const int t    = threadIdx.x;
    const int wid  = t >> 5;
    const int lane = t & 31;
    const int g    = lane >> 2;
    const int tq   = lane & 3;
    const int bh   = blockIdx.y, b = bh >> 2, h = bh & 3;
    const int q0   = blockIdx.x * 128;

    const uint32_t sQ = cvta_s(Qs);
    const uint32_t sK[2] = { cvta_s(Ks[0]), cvta_s(Ks[1]) };
    const uint32_t sV[2] = { cvta_s(Vs[0]), cvta_s(Vs[1]) };

    auto load_kv = [&](int tile, int stg) {
        const int j0 = tile << 6;
        int r = t >> 2, qq = t & 3;
        cp16(sK[stg] + r * (TST*2) + qq * 16, &k[((size_t)bh * S_ + j0 + r) * DH_ + qq * 8]);
        cp16(sV[stg] + r * (TST*2) + qq * 16, &v[((size_t)bh * S_ + j0 + r) * DH_ + qq * 8]);
    };

    // preload Q + first KV tile
#pragma unroll
    for (int i = 0; i < 2; i++) {
        int id = t + (i << 8);
        int r = id >> 2, qq = id & 3;
        cp16(sQ + r * (TST*2) + qq * 16, &q[((size_t)bh * S_ + q0 + r) * DH_ + qq * 8]);
    }
    load_kv(0, 0);
    CP_COMMIT();

    float o[4][4];
    float lg = 0.f, lg8 = 0.f;
#pragma unroll
    for (int nf = 0; nf < 4; nf++)
#pragma unroll
        for (int e = 0; e < 4; e++) o[nf][e] = 0.f;

    uint32_t af2[2][4];

    // ldmatrix lane-offsets
    const int aRow = wid * 16 + (lane & 15);
    const int aColX = (lane >> 4) * 8;
    const int bRow = (lane & 7) + ((lane >> 4) << 3);   // K (non-trans B)
    const int bColX = ((lane >> 3) & 1) * 8;
    const int vRow = (lane & 7) + (((lane >> 3) & 1) << 3);  // V (trans B)
    const int vColX = (lane >> 4) * 8;

    for (int it = 0; it < (S_ >> 6); it++) {
        const int stg = it & 1;
        if (it + 1 < (S_ >> 6)) { load_kv(it + 1, stg ^ 1); CP_COMMIT(); CP_WAIT(1); }
        else CP_WAIT(0);
        __syncthreads();

        if (it == 0) {
#pragma unroll
            for (int ks = 0; ks < 2; ks++)
                ldm_x4(af2[ks], sQ + (aRow * TST + ks * 16 + aColX) * 2);
        }

        // scores = Q @ K^T
        float sc[8][4];
#pragma unroll
        for (int nf = 0; nf < 8; nf++)
#pragma unroll
            for (int e = 0; e < 4; e++) sc[nf][e] = 0.f;
#pragma unroll
        for (int ks = 0; ks < 2; ks++) {
            const int kk = ks << 4;
#pragma unroll
            for (int pp = 0; pp < 4; pp++) {
                uint32_t r4[4];
                ldm_x4(r4, sK[stg] + ((pp * 16 + bRow) * TST + kk + bColX) * 2);
                uint32_t b0[2] = { r4[0], r4[1] }, b1[2] = { r4[2], r4[3] };
                mma16816(sc[pp*2],   af2[ks], b0);
                mma16816(sc[pp*2+1], af2[ks], b1);
            }
        }

        // p = ex2(s) (Q pre-scaled); accumulate l; pack PV A-fragments
        uint32_t pb[8][2];
#pragma unroll
        for (int nf = 0; nf < 8; nf++) {
            float p0 = ex2f(sc[nf][0]);
            float p1 = ex2f(sc[nf][1]);
            float p2 = ex2f(sc[nf][2]);
            float p3 = ex2f(sc[nf][3]);
            lg  += p0 + p1;
            lg8 += p2 + p3;
            pb[nf][0] = packbf2(p0, p1);
            pb[nf][1] = packbf2(p2, p3);
        }

        // O += P @ V
#pragma unroll
        for (int kf = 0; kf < 4; kf++) {
            uint32_t a4[4] = { pb[2*kf][0], pb[2*kf][1], pb[2*kf+1][0], pb[2*kf+1][1] };
#pragma unroll
            for (int pp = 0; pp < 2; pp++) {
                uint32_t r4[4];
                ldm_x4t(r4, sV[stg] + ((kf * 16 + vRow) * TST + pp * 16 + vColX) * 2);
                uint32_t b0[2] = { r4[0], r4[1] }, b1[2] = { r4[2], r4[3] };
                mma16816(o[pp*2],   a4, b0);
                mma16816(o[pp*2+1], a4, b1);
            }
        }
        __syncthreads();
    }

    lg  += __shfl_xor_sync(0xffffffffu, lg, 1);
    lg  += __shfl_xor_sync(0xffffffffu, lg, 2);
    lg8 += __shfl_xor_sync(0xffffffffu, lg8, 1);
    lg8 += __shfl_xor_sync(0xffffffffu, lg8, 2);
    const float inv0 = 1.f / lg;
    const float inv1 = 1.f / lg8;

    const int r0 = q0 + wid * 16 + g;
    const int r1 = r0 + 8;
#pragma unroll
    for (int nf = 0; nf < 4; nf++) {
        const int dd = nf * 8 + tq * 2;
        *reinterpret_cast<uint32_t*>(out + ((size_t)(b * S_ + r0)) * D_ + h * DH_ + dd) =
            packbf2(o[nf][0] * inv0, o[nf][1] * inv0);
        *reinterpret_cast<uint32_t*>(out + ((size_t)(b * S_ + r1)) * D_ + h * DH_ + dd) =
            packbf2(o[nf][2] * inv1, o[nf][3] * inv1);
    }
}

// ======================= Head: FC -> softmax -> rebalance =======================
__global__ __launch_bounds__(512)
void head_kernel(const float* __restrict__ hbuf, const float* __restrict__ fcw,
                 const float* __restrict__ fcb, float* __restrict__ out)
{
    __shared__ float logits[B_][OUT_];
    const int t = threadIdx.x;
    if (t < B_ * OUT_) {
        int b = t / OUT_;
        int o = t % OUT_;
        const float* hr = hbuf + ((size_t)(b * S_ + (S_ - 1))) * D_;
        float acc = fcb[o];
        for (int d = 0; d < D_; d++) acc += hr[d] * fcw[o * D_ + d];
        logits[b][o] = acc;
    }
    __syncthreads();
    if (t < B_) {
        const float UB = 0.3f, LB = 0.0f;
        float wv[OUT_], old[OUT_], wc[OUT_], res[OUT_];
        float mx = -1e30f;
        for (int o = 0; o < OUT_; o++) mx = fmaxf(mx, logits[t][o]);
        float sum = 0.f;
        for (int o = 0; o < OUT_; o++) { wv[o] = expf(logits[t][o] - mx); sum += wv[o]; }
        float inv = 1.f / sum;
        for (int o = 0; o < OUT_; o++) wv[o] *= inv;
        bool done = false;
        for (int o = 0; o < OUT_; o++) {
            old[o] = wv[o];
            wc[o]  = fminf(fmaxf(wv[o], LB), UB);
            res[o] = wv[o];
        }
        for (int it = 0; it < 16; it++) {
            float leftover = 0.f;
            for (int o = 0; o < OUT_; o++) leftover += old[o] - wc[o];
            float denom = 0.f;
            float noms[OUT_];
            for (int o = 0; o < OUT_; o++) {
                noms[o] = (wc[o] != UB) ? wc[o] : 0.f;
                denom += noms[o];
            }
            if (denom == 0.f) denom = 1.f;
            float cand[OUT_];
            bool any = false;
            for (int o = 0; o < OUT_; o++) {
                cand[o] = wc[o] + leftover * noms[o] / denom;
                if (cand[o] > UB) any = true;
            }
            if (!done)
                for (int o = 0; o < OUT_; o++) res[o] = cand[o];
            done = done || !any;
            if (!done) {
                for (int o = 0; o < OUT_; o++) {
                    old[o] = cand[o];
                    wc[o]  = fminf(fmaxf(cand[o], LB), UB);
                }
            }
        }
        for (int o = 0; o < OUT_; o++) out[t * OUT_ + o] = res[o];
    }
}

// ======================= launch =======================
extern "C" void kernel_launch(void* const* d_in, const int* in_sizes, int n_in,
                              void* d_out, int out_size)
{
    const float* x   = (const float*)d_in[0];
    const float* ipw = (const float*)d_in[1];
    const float* ipb = (const float*)d_in[2];
    const float* ow  = (const float*)d_in[3];
    const float* ob  = (const float*)d_in[4];
    const float* l1g = (const float*)d_in[5];
    const float* l1b = (const float*)d_in[6];
    const float* f1w = (const float*)d_in[7];
    const float* f1b = (const float*)d_in[8];
    const float* f2w = (const float*)d_in[9];
    const float* f2b = (const float*)d_in[10];
    const float* l2g = (const float*)d_in[11];
    const float* l2b = (const float*)d_in[12];
    const float* fcw = (const float*)d_in[13];
    const float* fcb = (const float*)d_in[14];

    __nv_bfloat16 *qb, *kb, *vb, *attnb, *hb, *ffb, *wip, *wout, *wf1, *wf2;
    float *h;
    cudaGetSymbolAddress((void**)&qb,    g_qb);
    cudaGetSymbolAddress((void**)&kb,    g_kb);
    cudaGetSymbolAddress((void**)&vb,    g_vb);
    cudaGetSymbolAddress((void**)&attnb, g_attnb);
    cudaGetSymbolAddress((void**)&hb,    g_hb);
    cudaGetSymbolAddress((void**)&h,     g_h);
    cudaGetSymbolAddress((void**)&ffb,   g_ffb);
    cudaGetSymbolAddress((void**)&wip,   g_wip);
    cudaGetSymbolAddress((void**)&wout,  g_wout);
    cudaGetSymbolAddress((void**)&wf1,   g_wf1);
    cudaGetSymbolAddress((void**)&wf2,   g_wf2);

    cvt_kernel<<<(L_*3*D_*D_)/1024, 256>>>(ipw, wip, L_*3*D_*D_);
    cvt_kernel<<<(L_*D_*D_)/1024,   256>>>(ow,  wout, L_*D_*D_);
    cvt_kernel<<<(L_*FF_*D_)/1024,  256>>>(f1w, wf1, L_*FF_*D_);
    cvt_kernel<<<(L_*D_*FF_)/1024,  256>>>(f2w, wf2, L_*D_*FF_);
    cvt_kernel<<<(M_*D_)/1024,      256>>>(x,   hb,  M_*D_);

    for (int l = 0; l < L_; l++) {
        const float* hinF = (l == 0) ? x : h;

        // QKV projection -> q/k/v bf16 [b,h,s,32] (q pre-scaled)
        mm_kernel<0><<<dim3(3, M_/128), 256>>>(
            hb, wip + (size_t)l*3*D_*D_, ipb + (size_t)l*3*D_,
            nullptr, nullptr, nullptr, nullptr, nullptr, qb, kb, vb, 3*D_, D_);

        // flash attention
        attn_kernel<<<dim3(S_/128, B_*H_), 256>>>(qb, kb, vb, attnb);

        // out projection + residual + LN1 -> h (fp32), hb (bf16)
        mm_kernel<2><<<dim3(1, M_/128), 256>>>(
            attnb, wout + (size_t)l*D_*D_, ob + (size_t)l*D_,
            hinF, l1g + (size_t)l*D_, l1b + (size_t)l*D_,
            h, hb, nullptr, nullptr, nullptr, D_, D_);

        // FF1 + relu -> ffb (bf16)
        mm_kernel<1><<<dim3(FF_/128, M_/128), 256>>>(
            hb, wf1 + (size_t)l*FF_*D_, f1b + (size_t)l*FF_,
            nullptr, nullptr, nullptr, nullptr, ffb, nullptr, nullptr, nullptr, FF_, D_);

        // FF2 + residual(h) + LN2 -> h, hb
        mm_kernel<2><<<dim3(1, M_/128), 256>>>(
            ffb, wf2 + (size_t)l*D_*FF_, f2b + (size_t)l*D_,
            h, l2g + (size_t)l*D_, l2b + (size_t)l*D_,
            h, hb, nullptr, nullptr, nullptr, D_, FF_);
    }

    head_kernel<<<1, 512>>>(h, fcw, fcb, (float*)d_out);
}